// round 16
// baseline (speedup 1.0000x reference)
#include <cuda_runtime.h>
#include <cuda_bf16.h>
#include <math.h>

#define NTOK 294      // 6*7*7 tokens per window
#define NWIN 256      // 16*16 windows
#define NHEAD 8
#define DH 32
#define DIM 256
#define QSCALE 0.17677669529663687f  // 32^-0.5

#define JT 320        // j padded to 40 n-tiles of 8 (5 chunks of 64)
#define BSTR 320      // bias row stride (cols 294..319 = -1e30)
#define KSTR3 40      // K smem stride: 40%32=8 -> conflict-free LDS.64 B frags
#define VTSTR3 328    // Vt stride: 328%32=8 -> conflict-free LDS.64 B frags

// -------- scratch (device globals; no allocations allowed) --------
__device__ float g_Q[(size_t)NWIN*NHEAD*NTOK*DH];
__device__ float g_K[(size_t)NWIN*NHEAD*NTOK*DH];
__device__ float g_V[(size_t)NWIN*NHEAD*NTOK*DH];
__device__ float g_O[(size_t)NWIN*NHEAD*NTOK*DH];
__device__ float g_bias[(size_t)NHEAD*NTOK*BSTR];

// ---- tf32 / async helpers ----
__device__ __forceinline__ unsigned cvt_tf32(float f) {
    unsigned u; asm("cvt.rna.tf32.f32 %0, %1;" : "=r"(u) : "f"(f)); return u;
}
#define MMA8(D, A, B)                                                         \
    asm volatile(                                                             \
        "mma.sync.aligned.m16n8k8.row.col.f32.tf32.tf32.f32 "                 \
        "{%0,%1,%2,%3}, {%4,%5,%6,%7}, {%8,%9}, {%0,%1,%2,%3};"               \
        : "+f"((D)[0]), "+f"((D)[1]), "+f"((D)[2]), "+f"((D)[3])              \
        : "r"((A)[0]), "r"((A)[1]), "r"((A)[2]), "r"((A)[3]),                 \
          "r"((B)[0]), "r"((B)[1]))

__device__ __forceinline__ void cp_async16(float* s, const float* g) {
    unsigned sa = (unsigned)__cvta_generic_to_shared(s);
    asm volatile("cp.async.cg.shared.global [%0], [%1], 16;" :: "r"(sa), "l"(g));
}
#define CP_COMMIT() asm volatile("cp.async.commit_group;")
#define CP_WAIT2()  asm volatile("cp.async.wait_group 2;")

#define STAGES 4
#define TSTR 20     // per-stage row stride in floats (16 data + 4 pad)
#define STAGE_WORDS (256 * TSTR)      // A[128][20] + B[128][20]
#define GEMM_SMEM (STAGES * STAGE_WORDS * 4)   // 81920 bytes

// ======================================================================
// 1) Bias matrix bias[h][i][jpad] with -1e30 padding cols
// ======================================================================
__global__ void bias_kernel(const float* __restrict__ table) {
    int i = blockIdx.x;
    int j = threadIdx.x;          // 0..319
    if (j >= NTOK) {
#pragma unroll
        for (int h = 0; h < NHEAD; h++)
            g_bias[((size_t)h * NTOK + i) * BSTR + j] = -1e30f;
        return;
    }
    int ai = i / 49, ri = i % 49, yi = ri / 7, xi = ri % 7;
    int aj = j / 49, rj = j % 49, yj = rj / 7, xj = rj % 7;
    int idx = (ai - aj + 5) * 169 + (yi - yj + 6) * 13 + (xi - xj + 6);
#pragma unroll
    for (int h = 0; h < NHEAD; h++)
        g_bias[((size_t)h * NTOK + i) * BSTR + j] = table[idx * NHEAD + h];
}

// ======================================================================
// 2) QKV projection: tf32 mma.sync, cp.async pipeline, k-permuted
//    LDS.64 fragment loads (slots = cols {2lt, 2lt+1}).
// ======================================================================
__global__ __launch_bounds__(256, 2) void qkv_gemm(
    const float* __restrict__ x, const float* __restrict__ w) {
    extern __shared__ float smf[];
    int tid = threadIdx.x;
    int bm = blockIdx.x, bn = blockIdx.y;
    int row = tid >> 2;           // 0..63
    int chunk = tid & 3;          // 4-float chunk within 16

    const float *ap0, *ap1;
    {
        int m0 = bm * 128 + row;
        int Bw = m0 / 294, t = m0 % 294, l = t / 49, r = t % 49;
        ap0 = x + ((size_t)((l * 256 + Bw) * 49 + r)) * 256;
        int m1 = m0 + 64;
        Bw = m1 / 294; t = m1 % 294; l = t / 49; r = t % 49;
        ap1 = x + ((size_t)((l * 256 + Bw) * 49 + r)) * 256;
    }
    const float* bp0 = w + (size_t)(bn * 128 + row) * 256;
    const float* bp1 = bp0 + (size_t)64 * 256;

    int wid = tid >> 5, lane = tid & 31;
    int g = lane >> 2, lt = lane & 3;
    int m0w = (wid & 1) * 64, n0w = (wid >> 1) * 32;

    float acc[4][4][4];
#pragma unroll
    for (int a = 0; a < 4; a++)
#pragma unroll
        for (int b = 0; b < 4; b++)
#pragma unroll
            for (int c = 0; c < 4; c++) acc[a][b][c] = 0.f;

    auto load_tile = [&](int s, int kt) {
        float* A = smf + s * STAGE_WORDS;
        float* B = A + 128 * TSTR;
        int k0 = kt * 16 + chunk * 4;
        cp_async16(A + row * TSTR + chunk * 4, ap0 + k0);
        cp_async16(A + (row + 64) * TSTR + chunk * 4, ap1 + k0);
        cp_async16(B + row * TSTR + chunk * 4, bp0 + k0);
        cp_async16(B + (row + 64) * TSTR + chunk * 4, bp1 + k0);
    };

#pragma unroll
    for (int s = 0; s < STAGES - 1; s++) { load_tile(s, s); CP_COMMIT(); }

    for (int t = 0; t < 16; t++) {
        CP_WAIT2();
        __syncthreads();
        int ld = t + STAGES - 1;
        if (ld < 16) load_tile(ld & 3, ld);
        CP_COMMIT();

        const float* A = smf + (t & 3) * STAGE_WORDS;
        const float* B = A + 128 * TSTR;
#pragma unroll
        for (int k8 = 0; k8 < 16; k8 += 8) {
            unsigned af[4][4], bf[4][2];
#pragma unroll
            for (int mt = 0; mt < 4; mt++) {
                int rb = m0w + mt * 16 + g;
                float2 a0 = *(const float2*)(A + rb * TSTR + k8 + 2 * lt);
                float2 a1 = *(const float2*)(A + (rb + 8) * TSTR + k8 + 2 * lt);
                af[mt][0] = cvt_tf32(a0.x);
                af[mt][1] = cvt_tf32(a1.x);
                af[mt][2] = cvt_tf32(a0.y);
                af[mt][3] = cvt_tf32(a1.y);
            }
#pragma unroll
            for (int nt = 0; nt < 4; nt++) {
                int cb = n0w + nt * 8 + g;
                float2 b = *(const float2*)(B + cb * TSTR + k8 + 2 * lt);
                bf[nt][0] = cvt_tf32(b.x);
                bf[nt][1] = cvt_tf32(b.y);
            }
#pragma unroll
            for (int mt = 0; mt < 4; mt++)
#pragma unroll
                for (int nt = 0; nt < 4; nt++)
                    MMA8(acc[mt][nt], af[mt], bf[nt]);
        }
    }

    // epilogue: scatter into Q/K/V
#pragma unroll
    for (int mt = 0; mt < 4; mt++) {
#pragma unroll
        for (int half = 0; half < 2; half++) {
            int m = bm * 128 + m0w + mt * 16 + g + half * 8;
            int Bw = m / 294, tt = m % 294;
            size_t mb = (size_t)Bw * 8 * NTOK + tt;
#pragma unroll
            for (int nt = 0; nt < 4; nt++) {
#pragma unroll
                for (int e = 0; e < 2; e++) {
                    int n = bn * 128 + n0w + nt * 8 + 2 * lt + e;
                    int part = n >> 8, rem = n & 255;
                    int head = rem >> 5, dh = rem & 31;
                    size_t o = (mb + (size_t)head * NTOK) * DH + dh;
                    float v = acc[mt][nt][half * 2 + e];
                    if (part == 0)      g_Q[o] = v * QSCALE;
                    else if (part == 1) g_K[o] = v;
                    else                g_V[o] = v;
                }
            }
        }
    }
}

// ======================================================================
// 3) Attention: warp-independent flash, shuffle-free AV, k-permuted
//    LDS.64 K fragments (d-cols {2lt,2lt+1}, Q frags match via LDG.64).
// ======================================================================
__global__ __launch_bounds__(256, 2) void attn_kernel() {
    int bh = blockIdx.x;            // Bw*8 + h
    int h = bh & 7;
    extern __shared__ unsigned smu[];
    unsigned* Ks = smu;                    // 320*40  = 12800
    unsigned* Vt = Ks + JT * KSTR3;        // 32*328  = 10496
    // total 23296 words = 93.2 KB -> 2 blocks/SM

    const float* Kg = g_K + (size_t)bh * NTOK * DH;
    const float* Vg = g_V + (size_t)bh * NTOK * DH;
    const float* Qg = g_Q + (size_t)bh * NTOK * DH;
    const float* Bbp = g_bias + (size_t)h * NTOK * BSTR;

    int tid = threadIdx.x;
    for (int idx = tid; idx < JT * DH; idx += 256) {
        int j = idx >> 5, d = idx & 31;
        float kv = (j < NTOK) ? Kg[j * DH + d] : 0.f;
        float vv = (j < NTOK) ? Vg[j * DH + d] : 0.f;
        Ks[j * KSTR3 + d] = cvt_tf32(kv);
        Vt[d * VTSTR3 + j] = cvt_tf32(vv);
    }
    __syncthreads();

    int w = tid >> 5, lane = tid & 31;
    int g = lane >> 2, lt = lane & 3;

    for (int tile = w; tile < 19; tile += 8) {
        int i0 = tile * 16;
        int r0 = i0 + g;     if (r0 >= NTOK) r0 = NTOK - 1;
        int r1 = i0 + g + 8; if (r1 >= NTOK) r1 = NTOK - 1;

        // Q A-frags, k-permuted: slots hold d-cols {2lt, 2lt+1}
        unsigned qf[4][4];
#pragma unroll
        for (int k8 = 0; k8 < 4; k8++) {
            float2 q0 = *(const float2*)(Qg + r0 * DH + k8 * 8 + 2 * lt);
            float2 q1 = *(const float2*)(Qg + r1 * DH + k8 * 8 + 2 * lt);
            qf[k8][0] = cvt_tf32(q0.x);
            qf[k8][1] = cvt_tf32(q1.x);
            qf[k8][2] = cvt_tf32(q0.y);
            qf[k8][3] = cvt_tf32(q1.y);
        }
        const float* br0 = Bbp + (size_t)r0 * BSTR;
        const float* br1 = Bbp + (size_t)r1 * BSTR;

        float m0 = -1e30f, m1 = -1e30f, l0 = 0.f, l1 = 0.f;
        float O[4][4];
#pragma unroll
        for (int dt = 0; dt < 4; dt++)
#pragma unroll
            for (int e = 0; e < 4; e++) O[dt][e] = 0.f;

        for (int c = 0; c < 5; c++) {
            // ---- QK for 8 n-tiles (64 cols), bias fused ----
            float s[8][4];
#pragma unroll
            for (int n = 0; n < 8; n++) {
                int nt = c * 8 + n;
                float acc[4] = {0.f, 0.f, 0.f, 0.f};
                const unsigned* kb = Ks + (nt * 8 + g) * KSTR3;
#pragma unroll
                for (int k8 = 0; k8 < 4; k8++) {
                    uint2 kv = *(const uint2*)(kb + k8 * 8 + 2 * lt);
                    unsigned bf[2] = { kv.x, kv.y };
                    MMA8(acc, qf[k8], bf);
                }
                float2 b0v = *(const float2*)(br0 + nt * 8 + 2 * lt);
                float2 b1v = *(const float2*)(br1 + nt * 8 + 2 * lt);
                s[n][0] = acc[0] + b0v.x; s[n][1] = acc[1] + b0v.y;
                s[n][2] = acc[2] + b1v.x; s[n][3] = acc[3] + b1v.y;
            }

            // ---- online softmax update ----
            float cm0 = -1e30f, cm1 = -1e30f;
#pragma unroll
            for (int n = 0; n < 8; n++) {
                cm0 = fmaxf(cm0, fmaxf(s[n][0], s[n][1]));
                cm1 = fmaxf(cm1, fmaxf(s[n][2], s[n][3]));
            }
            cm0 = fmaxf(cm0, __shfl_xor_sync(0xffffffffu, cm0, 1));
            cm0 = fmaxf(cm0, __shfl_xor_sync(0xffffffffu, cm0, 2));
            cm1 = fmaxf(cm1, __shfl_xor_sync(0xffffffffu, cm1, 1));
            cm1 = fmaxf(cm1, __shfl_xor_sync(0xffffffffu, cm1, 2));
            float nm0 = fmaxf(m0, cm0), nm1 = fmaxf(m1, cm1);
            float f0 = __expf(m0 - nm0), f1 = __expf(m1 - nm1);
            m0 = nm0; m1 = nm1;

            float sum0 = 0.f, sum1 = 0.f;
#pragma unroll
            for (int n = 0; n < 8; n++) {
                s[n][0] = __expf(s[n][0] - m0); sum0 += s[n][0];
                s[n][1] = __expf(s[n][1] - m0); sum0 += s[n][1];
                s[n][2] = __expf(s[n][2] - m1); sum1 += s[n][2];
                s[n][3] = __expf(s[n][3] - m1); sum1 += s[n][3];
            }
            sum0 += __shfl_xor_sync(0xffffffffu, sum0, 1);
            sum0 += __shfl_xor_sync(0xffffffffu, sum0, 2);
            sum1 += __shfl_xor_sync(0xffffffffu, sum1, 1);
            sum1 += __shfl_xor_sync(0xffffffffu, sum1, 2);
            l0 = l0 * f0 + sum0;
            l1 = l1 * f1 + sum1;

#pragma unroll
            for (int dt = 0; dt < 4; dt++) {
                O[dt][0] *= f0; O[dt][1] *= f0;
                O[dt][2] *= f1; O[dt][3] *= f1;
            }

            // ---- AV, shuffle-free (j-permuted: slot lt -> j0+2lt,
            //      slot lt+4 -> j0+2lt+1) ----
#pragma unroll
            for (int n = 0; n < 8; n++) {
                int j0 = (c * 8 + n) * 8;
                unsigned af[4];
                af[0] = cvt_tf32(s[n][0]);
                af[1] = cvt_tf32(s[n][2]);
                af[2] = cvt_tf32(s[n][1]);
                af[3] = cvt_tf32(s[n][3]);
#pragma unroll
                for (int dt = 0; dt < 4; dt++) {
                    const unsigned* vb = Vt + (dt * 8 + g) * VTSTR3;
                    uint2 vv = *(const uint2*)(vb + j0 + 2 * lt);
                    unsigned bf[2] = { vv.x, vv.y };
                    MMA8(O[dt], af, bf);
                }
            }
        }

        // ---- finalize + store ----
        float inv0 = 1.f / l0, inv1 = 1.f / l1;
        int ia = i0 + g, ib = i0 + g + 8;
        float* ob = g_O + (size_t)bh * NTOK * DH;
#pragma unroll
        for (int dt = 0; dt < 4; dt++) {
            if (ia < NTOK)
                *(float2*)(ob + ia * DH + dt * 8 + 2 * lt) =
                    make_float2(O[dt][0] * inv0, O[dt][1] * inv0);
            if (ib < NTOK)
                *(float2*)(ob + ib * DH + dt * 8 + 2 * lt) =
                    make_float2(O[dt][2] * inv1, O[dt][3] * inv1);
        }
    }
}

// ======================================================================
// 4) Output projection: tf32 mma.sync, cp.async pipeline, k-permuted
//    LDS.64 fragment loads.
// ======================================================================
__global__ __launch_bounds__(256, 2) void out_gemm(
    const float* __restrict__ w, float* __restrict__ out) {
    extern __shared__ float smf[];
    int tid = threadIdx.x;
    int bm = blockIdx.x, bn = blockIdx.y;
    int row = tid >> 2;
    int chunk = tid & 3;

    int m0 = bm * 128 + row;
    int Bw0 = m0 / 294, t0 = m0 % 294;
    int m1 = m0 + 64;
    int Bw1 = m1 / 294, t1 = m1 % 294;
    const float* abase0 = g_O + ((size_t)Bw0 * 8 * NTOK + t0) * DH;
    const float* abase1 = g_O + ((size_t)Bw1 * 8 * NTOK + t1) * DH;

    const float* bp0 = w + (size_t)(bn * 128 + row) * 256;
    const float* bp1 = bp0 + (size_t)64 * 256;

    int wid = tid >> 5, lane = tid & 31;
    int g = lane >> 2, lt = lane & 3;
    int m0w = (wid & 1) * 64, n0w = (wid >> 1) * 32;

    float acc[4][4][4];
#pragma unroll
    for (int a = 0; a < 4; a++)
#pragma unroll
        for (int b = 0; b < 4; b++)
#pragma unroll
            for (int c = 0; c < 4; c++) acc[a][b][c] = 0.f;

    auto load_tile = [&](int s, int kt) {
        float* A = smf + s * STAGE_WORDS;
        float* B = A + 128 * TSTR;
        int k = kt * 16 + chunk * 4;         // 16B chunk stays in one head
        int head = k >> 5, dh = k & 31;
        size_t go = (size_t)head * NTOK * DH + dh;
        cp_async16(A + row * TSTR + chunk * 4, abase0 + go);
        cp_async16(A + (row + 64) * TSTR + chunk * 4, abase1 + go);
        cp_async16(B + row * TSTR + chunk * 4, bp0 + k);
        cp_async16(B + (row + 64) * TSTR + chunk * 4, bp1 + k);
    };

#pragma unroll
    for (int s = 0; s < STAGES - 1; s++) { load_tile(s, s); CP_COMMIT(); }

    for (int t = 0; t < 16; t++) {
        CP_WAIT2();
        __syncthreads();
        int ld = t + STAGES - 1;
        if (ld < 16) load_tile(ld & 3, ld);
        CP_COMMIT();

        const float* A = smf + (t & 3) * STAGE_WORDS;
        const float* B = A + 128 * TSTR;
#pragma unroll
        for (int k8 = 0; k8 < 16; k8 += 8) {
            unsigned af[4][4], bf[4][2];
#pragma unroll
            for (int mt = 0; mt < 4; mt++) {
                int rb = m0w + mt * 16 + g;
                float2 a0 = *(const float2*)(A + rb * TSTR + k8 + 2 * lt);
                float2 a1 = *(const float2*)(A + (rb + 8) * TSTR + k8 + 2 * lt);
                af[mt][0] = cvt_tf32(a0.x);
                af[mt][1] = cvt_tf32(a1.x);
                af[mt][2] = cvt_tf32(a0.y);
                af[mt][3] = cvt_tf32(a1.y);
            }
#pragma unroll
            for (int nt = 0; nt < 4; nt++) {
                int cb = n0w + nt * 8 + g;
                float2 b = *(const float2*)(B + cb * TSTR + k8 + 2 * lt);
                bf[nt][0] = cvt_tf32(b.x);
                bf[nt][1] = cvt_tf32(b.y);
            }
#pragma unroll
            for (int mt = 0; mt < 4; mt++)
#pragma unroll
                for (int nt = 0; nt < 4; nt++)
                    MMA8(acc[mt][nt], af[mt], bf[nt]);
        }
    }

#pragma unroll
    for (int mt = 0; mt < 4; mt++) {
#pragma unroll
        for (int half = 0; half < 2; half++) {
            int m = bm * 128 + m0w + mt * 16 + g + half * 8;
            int Bw = m / 294, tt = m % 294, l = tt / 49, r = tt % 49;
            float* op = out + ((size_t)((l * 256 + Bw) * 49 + r)) * 256;
#pragma unroll
            for (int nt = 0; nt < 4; nt++) {
                int n = bn * 128 + n0w + nt * 8 + 2 * lt;
                float2 v = make_float2(acc[mt][nt][half * 2],
                                       acc[mt][nt][half * 2 + 1]);
                *(float2*)(op + n) = v;
            }
        }
    }
}

// ======================================================================
extern "C" void kernel_launch(void* const* d_in, const int* in_sizes, int n_in,
                              void* d_out, int out_size) {
    const float* x          = (const float*)d_in[0];
    const float* w_qkv      = (const float*)d_in[1];
    const float* w_out      = (const float*)d_in[2];
    const float* bias_table = (const float*)d_in[3];
    float* out = (float*)d_out;

    bias_kernel<<<NTOK, BSTR>>>(bias_table);

    cudaFuncSetAttribute(qkv_gemm, cudaFuncAttributeMaxDynamicSharedMemorySize, GEMM_SMEM);
    qkv_gemm<<<dim3(588, 6), 256, GEMM_SMEM>>>(x, w_qkv);

    int smem = (JT * KSTR3 + DH * VTSTR3) * (int)sizeof(unsigned);
    cudaFuncSetAttribute(attn_kernel, cudaFuncAttributeMaxDynamicSharedMemorySize, smem);
    attn_kernel<<<NWIN * NHEAD, 256, smem>>>();

    cudaFuncSetAttribute(out_gemm, cudaFuncAttributeMaxDynamicSharedMemorySize, GEMM_SMEM);
    out_gemm<<<dim3(588, 2), 256, GEMM_SMEM>>>(w_out, out);
}

// round 17
// speedup vs baseline: 1.5000x; 1.5000x over previous
#include <cuda_runtime.h>
#include <cuda_fp16.h>
#include <math.h>

#define NTOK 294      // 6*7*7 tokens per window
#define NWIN 256      // 16*16 windows
#define NHEAD 8
#define DH 32
#define DIM 256
#define QSCALE 0.17677669529663687f  // 32^-0.5

#define JT 320        // j padded to 40 n-tiles of 8
#define BSTR 320      // bias row stride (cols 294..319 = -1e30)
#define KSH 40        // Ks row stride in halves (20 words -> conflict-free)
#define VTH 328       // Vt row stride in halves (164 words = 4 mod 32)

#define XELEMS (6 * 16 * 16 * 7 * 7 * 256)   // 19,267,584

// -------- scratch (device globals; no allocations allowed) --------
__device__ __half g_Qh[(size_t)NWIN*NHEAD*NTOK*DH];
__device__ __half g_Kh[(size_t)NWIN*NHEAD*NTOK*DH];
__device__ __half g_Vh[(size_t)NWIN*NHEAD*NTOK*DH];
__device__ __half g_Oh[(size_t)NWIN*NHEAD*NTOK*DH];
__device__ float  g_bias[(size_t)NHEAD*NTOK*BSTR];
__device__ __half g_xh[(size_t)XELEMS];
__device__ __half g_wqh[(size_t)768 * 256];
__device__ __half g_woh[(size_t)256 * 256];

// ---- helpers ----
__device__ __forceinline__ unsigned h2u(__half2 h) {
    return *reinterpret_cast<unsigned*>(&h);
}
#define MMA16(D, A, B)                                                        \
    asm volatile(                                                             \
        "mma.sync.aligned.m16n8k16.row.col.f32.f16.f16.f32 "                  \
        "{%0,%1,%2,%3}, {%4,%5,%6,%7}, {%8,%9}, {%0,%1,%2,%3};"               \
        : "+f"((D)[0]), "+f"((D)[1]), "+f"((D)[2]), "+f"((D)[3])              \
        : "r"((A)[0]), "r"((A)[1]), "r"((A)[2]), "r"((A)[3]),                 \
          "r"((B)[0]), "r"((B)[1]))

__device__ __forceinline__ void cp_async16(void* s, const void* g) {
    unsigned sa = (unsigned)__cvta_generic_to_shared(s);
    asm volatile("cp.async.cg.shared.global [%0], [%1], 16;" :: "r"(sa), "l"(g));
}
#define CP_COMMIT() asm volatile("cp.async.commit_group;")
#define CP_WAIT2()  asm volatile("cp.async.wait_group 2;")

#define STAGES 4
#define RSH 40      // GEMM stage row stride in halves (32 data + 8 pad)
#define STAGE_HALVES (256 * RSH)           // A[128][40] + B[128][40]
#define GEMM_SMEM (STAGES * STAGE_HALVES * 2)   // 81920 bytes

// ======================================================================
// 0) Producer conversions to fp16
// ======================================================================
__global__ void cvt_x_kernel(const float* __restrict__ x) {
    int i = (blockIdx.x * 256 + threadIdx.x) * 8;
    float4 a = *(const float4*)(x + i);
    float4 b = *(const float4*)(x + i + 4);
    __half2 h0 = __floats2half2_rn(a.x, a.y);
    __half2 h1 = __floats2half2_rn(a.z, a.w);
    __half2 h2 = __floats2half2_rn(b.x, b.y);
    __half2 h3 = __floats2half2_rn(b.z, b.w);
    *(uint4*)(g_xh + i) = make_uint4(h2u(h0), h2u(h1), h2u(h2), h2u(h3));
}
__global__ void cvt_w_kernel(const float* __restrict__ wq,
                             const float* __restrict__ wo) {
    int i = (blockIdx.x * 256 + threadIdx.x) * 8;
    if (i < 768 * 256) {
        float4 a = *(const float4*)(wq + i);
        float4 b = *(const float4*)(wq + i + 4);
        *(uint4*)(g_wqh + i) = make_uint4(
            h2u(__floats2half2_rn(a.x, a.y)), h2u(__floats2half2_rn(a.z, a.w)),
            h2u(__floats2half2_rn(b.x, b.y)), h2u(__floats2half2_rn(b.z, b.w)));
    }
    if (i < 256 * 256) {
        float4 a = *(const float4*)(wo + i);
        float4 b = *(const float4*)(wo + i + 4);
        *(uint4*)(g_woh + i) = make_uint4(
            h2u(__floats2half2_rn(a.x, a.y)), h2u(__floats2half2_rn(a.z, a.w)),
            h2u(__floats2half2_rn(b.x, b.y)), h2u(__floats2half2_rn(b.z, b.w)));
    }
}

// ======================================================================
// 1) Bias matrix bias[h][i][jpad] with -1e30 padding cols
// ======================================================================
__global__ void bias_kernel(const float* __restrict__ table) {
    int i = blockIdx.x;
    int j = threadIdx.x;          // 0..319
    if (j >= NTOK) {
#pragma unroll
        for (int h = 0; h < NHEAD; h++)
            g_bias[((size_t)h * NTOK + i) * BSTR + j] = -1e30f;
        return;
    }
    int ai = i / 49, ri = i % 49, yi = ri / 7, xi = ri % 7;
    int aj = j / 49, rj = j % 49, yj = rj / 7, xj = rj % 7;
    int idx = (ai - aj + 5) * 169 + (yi - yj + 6) * 13 + (xi - xj + 6);
#pragma unroll
    for (int h = 0; h < NHEAD; h++)
        g_bias[((size_t)h * NTOK + i) * BSTR + j] = table[idx * NHEAD + h];
}

// ======================================================================
// 2) QKV projection: fp16 m16n8k16, BK=32, 4-stage cp.async.
// ======================================================================
__global__ __launch_bounds__(256, 2) void qkv_gemm() {
    extern __shared__ __half smh[];
    int tid = threadIdx.x;
    int bm = blockIdx.x, bn = blockIdx.y;
    int row = tid >> 2;           // 0..63
    int chunk = tid & 3;          // 8-half (16B) chunk within 32

    const __half *ap0, *ap1;
    {
        int m0 = bm * 128 + row;
        int Bw = m0 / 294, t = m0 % 294, l = t / 49, r = t % 49;
        ap0 = g_xh + ((size_t)((l * 256 + Bw) * 49 + r)) * 256;
        int m1 = m0 + 64;
        Bw = m1 / 294; t = m1 % 294; l = t / 49; r = t % 49;
        ap1 = g_xh + ((size_t)((l * 256 + Bw) * 49 + r)) * 256;
    }
    const __half* bp0 = g_wqh + (size_t)(bn * 128 + row) * 256;
    const __half* bp1 = bp0 + (size_t)64 * 256;

    int wid = tid >> 5, lane = tid & 31;
    int g = lane >> 2, lt = lane & 3;
    int m0w = (wid & 1) * 64, n0w = (wid >> 1) * 32;

    float acc[4][4][4];
#pragma unroll
    for (int a = 0; a < 4; a++)
#pragma unroll
        for (int b = 0; b < 4; b++)
#pragma unroll
            for (int c = 0; c < 4; c++) acc[a][b][c] = 0.f;

    auto load_tile = [&](int s, int kt) {
        __half* A = smh + s * STAGE_HALVES;
        __half* B = A + 128 * RSH;
        int k0 = kt * 32 + chunk * 8;
        cp_async16(A + row * RSH + chunk * 8, ap0 + k0);
        cp_async16(A + (row + 64) * RSH + chunk * 8, ap1 + k0);
        cp_async16(B + row * RSH + chunk * 8, bp0 + k0);
        cp_async16(B + (row + 64) * RSH + chunk * 8, bp1 + k0);
    };

#pragma unroll
    for (int s = 0; s < STAGES - 1; s++) { load_tile(s, s); CP_COMMIT(); }

    for (int t = 0; t < 8; t++) {
        CP_WAIT2();
        __syncthreads();
        int ld = t + STAGES - 1;
        if (ld < 8) load_tile(ld & 3, ld);
        CP_COMMIT();

        const __half* A = smh + (t & 3) * STAGE_HALVES;
        const __half* B = A + 128 * RSH;
#pragma unroll
        for (int k16 = 0; k16 < 32; k16 += 16) {
            unsigned af[4][4], bf[4][2];
#pragma unroll
            for (int mt = 0; mt < 4; mt++) {
                int rb = m0w + mt * 16 + g;
                af[mt][0] = *(const unsigned*)(A + rb * RSH + k16 + 2 * lt);
                af[mt][1] = *(const unsigned*)(A + (rb + 8) * RSH + k16 + 2 * lt);
                af[mt][2] = *(const unsigned*)(A + rb * RSH + k16 + 2 * lt + 8);
                af[mt][3] = *(const unsigned*)(A + (rb + 8) * RSH + k16 + 2 * lt + 8);
            }
#pragma unroll
            for (int nt = 0; nt < 4; nt++) {
                int cb = n0w + nt * 8 + g;
                bf[nt][0] = *(const unsigned*)(B + cb * RSH + k16 + 2 * lt);
                bf[nt][1] = *(const unsigned*)(B + cb * RSH + k16 + 2 * lt + 8);
            }
#pragma unroll
            for (int mt = 0; mt < 4; mt++)
#pragma unroll
                for (int nt = 0; nt < 4; nt++)
                    MMA16(acc[mt][nt], af[mt], bf[nt]);
        }
    }

    // epilogue: scatter half2 pairs into Q/K/V
#pragma unroll
    for (int mt = 0; mt < 4; mt++) {
#pragma unroll
        for (int half = 0; half < 2; half++) {
            int m = bm * 128 + m0w + mt * 16 + g + half * 8;
            int Bw = m / 294, tt = m % 294;
            size_t mb = (size_t)Bw * 8 * NTOK + tt;
#pragma unroll
            for (int nt = 0; nt < 4; nt++) {
                int n = bn * 128 + n0w + nt * 8 + 2 * lt;
                int part = n >> 8, rem = n & 255;
                int head = rem >> 5, dh = rem & 31;
                size_t o = (mb + (size_t)head * NTOK) * DH + dh;
                float v0 = acc[mt][nt][half * 2];
                float v1 = acc[mt][nt][half * 2 + 1];
                if (part == 0)
                    *(unsigned*)(g_Qh + o) =
                        h2u(__floats2half2_rn(v0 * QSCALE, v1 * QSCALE));
                else if (part == 1)
                    *(unsigned*)(g_Kh + o) = h2u(__floats2half2_rn(v0, v1));
                else
                    *(unsigned*)(g_Vh + o) = h2u(__floats2half2_rn(v0, v1));
            }
        }
    }
}

// ======================================================================
// 3) Attention: warp-independent flash, fp16 MMAs (K=32 -> 2 QK MMAs
//    per n-tile; AV pairs adjacent n-tiles into one k16 MMA).
// ======================================================================
__global__ __launch_bounds__(256, 2) void attn_kernel() {
    int bh = blockIdx.x;            // Bw*8 + h
    int h = bh & 7;
    extern __shared__ __half smh[];
    __half* Ks = smh;                      // 320*40 halves
    __half* Vt = smh + JT * KSH;           // 32*328 halves
    // total 23296 halves = 46.6 KB -> 2 blocks/SM

    const __half* Kg = g_Kh + (size_t)bh * NTOK * DH;
    const __half* Vg = g_Vh + (size_t)bh * NTOK * DH;
    const __half* Qg = g_Qh + (size_t)bh * NTOK * DH;
    const float* Bbp = g_bias + (size_t)h * NTOK * BSTR;

    int tid = threadIdx.x;
    {   // K rows: copy as 4B words, zero-pad
        unsigned* Ksw = (unsigned*)Ks;
        const unsigned* Kw = (const unsigned*)Kg;
        for (int idx = tid; idx < JT * 16; idx += 256) {
            int j = idx >> 4, d2 = idx & 15;
            Ksw[j * (KSH / 2) + d2] = (j < NTOK) ? Kw[j * 16 + d2] : 0u;
        }
        // V transpose, half scatter
        for (int idx = tid; idx < JT * DH; idx += 256) {
            int j = idx >> 5, d = idx & 31;
            Vt[d * VTH + j] = (j < NTOK) ? Vg[j * DH + d] : __half(0.f);
        }
    }
    __syncthreads();

    int w = tid >> 5, lane = tid & 31;
    int g = lane >> 2, lt = lane & 3;

    for (int tile = w; tile < 19; tile += 8) {
        int i0 = tile * 16;
        int r0 = i0 + g;     if (r0 >= NTOK) r0 = NTOK - 1;
        int r1 = i0 + g + 8; if (r1 >= NTOK) r1 = NTOK - 1;

        // Q A-frags for the 2 k16 steps
        unsigned qf[2][4];
#pragma unroll
        for (int ks = 0; ks < 2; ks++) {
            int k16 = ks * 16;
            qf[ks][0] = *(const unsigned*)(Qg + r0 * DH + k16 + 2 * lt);
            qf[ks][1] = *(const unsigned*)(Qg + r1 * DH + k16 + 2 * lt);
            qf[ks][2] = *(const unsigned*)(Qg + r0 * DH + k16 + 2 * lt + 8);
            qf[ks][3] = *(const unsigned*)(Qg + r1 * DH + k16 + 2 * lt + 8);
        }
        const float* br0 = Bbp + (size_t)r0 * BSTR;
        const float* br1 = Bbp + (size_t)r1 * BSTR;

        float m0 = -1e30f, m1 = -1e30f, l0 = 0.f, l1 = 0.f;
        float O[4][4];
#pragma unroll
        for (int dt = 0; dt < 4; dt++)
#pragma unroll
            for (int e = 0; e < 4; e++) O[dt][e] = 0.f;

        for (int c = 0; c < 5; c++) {
            // ---- QK for 8 n-tiles, bias fused ----
            float s[8][4];
#pragma unroll
            for (int n = 0; n < 8; n++) {
                int nt = c * 8 + n;
                float acc[4] = {0.f, 0.f, 0.f, 0.f};
                const __half* kb = Ks + (nt * 8 + g) * KSH;
#pragma unroll
                for (int ks = 0; ks < 2; ks++) {
                    int k16 = ks * 16;
                    unsigned bf[2] = {
                        *(const unsigned*)(kb + k16 + 2 * lt),
                        *(const unsigned*)(kb + k16 + 2 * lt + 8) };
                    MMA16(acc, qf[ks], bf);
                }
                float2 b0v = *(const float2*)(br0 + nt * 8 + 2 * lt);
                float2 b1v = *(const float2*)(br1 + nt * 8 + 2 * lt);
                s[n][0] = acc[0] + b0v.x; s[n][1] = acc[1] + b0v.y;
                s[n][2] = acc[2] + b1v.x; s[n][3] = acc[3] + b1v.y;
            }

            // ---- online softmax update ----
            float cm0 = -1e30f, cm1 = -1e30f;
#pragma unroll
            for (int n = 0; n < 8; n++) {
                cm0 = fmaxf(cm0, fmaxf(s[n][0], s[n][1]));
                cm1 = fmaxf(cm1, fmaxf(s[n][2], s[n][3]));
            }
            cm0 = fmaxf(cm0, __shfl_xor_sync(0xffffffffu, cm0, 1));
            cm0 = fmaxf(cm0, __shfl_xor_sync(0xffffffffu, cm0, 2));
            cm1 = fmaxf(cm1, __shfl_xor_sync(0xffffffffu, cm1, 1));
            cm1 = fmaxf(cm1, __shfl_xor_sync(0xffffffffu, cm1, 2));
            float nm0 = fmaxf(m0, cm0), nm1 = fmaxf(m1, cm1);
            float f0 = __expf(m0 - nm0), f1 = __expf(m1 - nm1);
            m0 = nm0; m1 = nm1;

            float sum0 = 0.f, sum1 = 0.f;
#pragma unroll
            for (int n = 0; n < 8; n++) {
                s[n][0] = __expf(s[n][0] - m0); sum0 += s[n][0];
                s[n][1] = __expf(s[n][1] - m0); sum0 += s[n][1];
                s[n][2] = __expf(s[n][2] - m1); sum1 += s[n][2];
                s[n][3] = __expf(s[n][3] - m1); sum1 += s[n][3];
            }
            sum0 += __shfl_xor_sync(0xffffffffu, sum0, 1);
            sum0 += __shfl_xor_sync(0xffffffffu, sum0, 2);
            sum1 += __shfl_xor_sync(0xffffffffu, sum1, 1);
            sum1 += __shfl_xor_sync(0xffffffffu, sum1, 2);
            l0 = l0 * f0 + sum0;
            l1 = l1 * f1 + sum1;

#pragma unroll
            for (int dt = 0; dt < 4; dt++) {
                O[dt][0] *= f0; O[dt][1] *= f0;
                O[dt][2] *= f1; O[dt][3] *= f1;
            }

            // ---- AV: pair adjacent n-tiles into one k16 MMA.
            //      j-permutation: k slot 2lt+e -> j0+2lt+e (group n),
            //      k slot 2lt+8+e -> group n+1.  D-frag halves pack
            //      directly into the A-frag half2 slots. ----
#pragma unroll
            for (int np = 0; np < 4; np++) {
                int n = 2 * np;
                int j0 = (c * 8 + n) * 8;
                unsigned af[4];
                af[0] = h2u(__floats2half2_rn(s[n][0],     s[n][1]));
                af[1] = h2u(__floats2half2_rn(s[n][2],     s[n][3]));
                af[2] = h2u(__floats2half2_rn(s[n + 1][0], s[n + 1][1]));
                af[3] = h2u(__floats2half2_rn(s[n + 1][2], s[n + 1][3]));
#pragma unroll
                for (int dt = 0; dt < 4; dt++) {
                    const __half* vb = Vt + (dt * 8 + g) * VTH;
                    unsigned bf[2] = {
                        *(const unsigned*)(vb + j0 + 2 * lt),
                        *(const unsigned*)(vb + j0 + 8 + 2 * lt) };
                    MMA16(O[dt], af, bf);
                }
            }
        }

        // ---- finalize + store (half2) ----
        float inv0 = 1.f / l0, inv1 = 1.f / l1;
        int ia = i0 + g, ib = i0 + g + 8;
        __half* ob = g_Oh + (size_t)bh * NTOK * DH;
#pragma unroll
        for (int dt = 0; dt < 4; dt++) {
            if (ia < NTOK)
                *(unsigned*)(ob + ia * DH + dt * 8 + 2 * lt) =
                    h2u(__floats2half2_rn(O[dt][0] * inv0, O[dt][1] * inv0));
            if (ib < NTOK)
                *(unsigned*)(ob + ib * DH + dt * 8 + 2 * lt) =
                    h2u(__floats2half2_rn(O[dt][2] * inv1, O[dt][3] * inv1));
        }
    }
}

// ======================================================================
// 4) Output projection: fp16 m16n8k16, BK=32, cp.async; fp32 output.
// ======================================================================
__global__ __launch_bounds__(256, 2) void out_gemm(float* __restrict__ out) {
    extern __shared__ __half smh[];
    int tid = threadIdx.x;
    int bm = blockIdx.x, bn = blockIdx.y;
    int row = tid >> 2;
    int chunk = tid & 3;

    int m0 = bm * 128 + row;
    int Bw0 = m0 / 294, t0 = m0 % 294;
    int m1 = m0 + 64;
    int Bw1 = m1 / 294, t1 = m1 % 294;
    const __half* abase0 = g_Oh + ((size_t)Bw0 * 8 * NTOK + t0) * DH;
    const __half* abase1 = g_Oh + ((size_t)Bw1 * 8 * NTOK + t1) * DH;

    const __half* bp0 = g_woh + (size_t)(bn * 128 + row) * 256;
    const __half* bp1 = bp0 + (size_t)64 * 256;

    int wid = tid >> 5, lane = tid & 31;
    int g = lane >> 2, lt = lane & 3;
    int m0w = (wid & 1) * 64, n0w = (wid >> 1) * 32;

    float acc[4][4][4];
#pragma unroll
    for (int a = 0; a < 4; a++)
#pragma unroll
        for (int b = 0; b < 4; b++)
#pragma unroll
            for (int c = 0; c < 4; c++) acc[a][b][c] = 0.f;

    auto load_tile = [&](int s, int kt) {
        __half* A = smh + s * STAGE_HALVES;
        __half* B = A + 128 * RSH;
        int k = kt * 32 + chunk * 8;   // 8-half chunk stays in one head
        int head = k >> 5, dh = k & 31;
        size_t go = (size_t)head * NTOK * DH + dh;
        cp_async16(A + row * RSH + chunk * 8, abase0 + go);
        cp_async16(A + (row + 64) * RSH + chunk * 8, abase1 + go);
        cp_async16(B + row * RSH + chunk * 8, bp0 + k);
        cp_async16(B + (row + 64) * RSH + chunk * 8, bp1 + k);
    };

#pragma unroll
    for (int s = 0; s < STAGES - 1; s++) { load_tile(s, s); CP_COMMIT(); }

    for (int t = 0; t < 8; t++) {
        CP_WAIT2();
        __syncthreads();
        int ld = t + STAGES - 1;
        if (ld < 8) load_tile(ld & 3, ld);
        CP_COMMIT();

        const __half* A = smh + (t & 3) * STAGE_HALVES;
        const __half* B = A + 128 * RSH;
#pragma unroll
        for (int k16 = 0; k16 < 32; k16 += 16) {
            unsigned af[4][4], bf[4][2];
#pragma unroll
            for (int mt = 0; mt < 4; mt++) {
                int rb = m0w + mt * 16 + g;
                af[mt][0] = *(const unsigned*)(A + rb * RSH + k16 + 2 * lt);
                af[mt][1] = *(const unsigned*)(A + (rb + 8) * RSH + k16 + 2 * lt);
                af[mt][2] = *(const unsigned*)(A + rb * RSH + k16 + 2 * lt + 8);
                af[mt][3] = *(const unsigned*)(A + (rb + 8) * RSH + k16 + 2 * lt + 8);
            }
#pragma unroll
            for (int nt = 0; nt < 4; nt++) {
                int cb = n0w + nt * 8 + g;
                bf[nt][0] = *(const unsigned*)(B + cb * RSH + k16 + 2 * lt);
                bf[nt][1] = *(const unsigned*)(B + cb * RSH + k16 + 2 * lt + 8);
            }
#pragma unroll
            for (int mt = 0; mt < 4; mt++)
#pragma unroll
                for (int nt = 0; nt < 4; nt++)
                    MMA16(acc[mt][nt], af[mt], bf[nt]);
        }
    }

#pragma unroll
    for (int mt = 0; mt < 4; mt++) {
#pragma unroll
        for (int half = 0; half < 2; half++) {
            int m = bm * 128 + m0w + mt * 16 + g + half * 8;
            int Bw = m / 294, tt = m % 294, l = tt / 49, r = tt % 49;
            float* op = out + ((size_t)((l * 256 + Bw) * 49 + r)) * 256;
#pragma unroll
            for (int nt = 0; nt < 4; nt++) {
                int n = bn * 128 + n0w + nt * 8 + 2 * lt;
                float2 v = make_float2(acc[mt][nt][half * 2],
                                       acc[mt][nt][half * 2 + 1]);
                *(float2*)(op + n) = v;
            }
        }
    }
}

// ======================================================================
extern "C" void kernel_launch(void* const* d_in, const int* in_sizes, int n_in,
                              void* d_out, int out_size) {
    const float* x          = (const float*)d_in[0];
    const float* w_qkv      = (const float*)d_in[1];
    const float* w_out      = (const float*)d_in[2];
    const float* bias_table = (const float*)d_in[3];
    float* out = (float*)d_out;

    cvt_x_kernel<<<XELEMS / 2048, 256>>>(x);
    cvt_w_kernel<<<(768 * 256 / 8 + 255) / 256, 256>>>(w_qkv, w_out);
    bias_kernel<<<NTOK, BSTR>>>(bias_table);

    cudaFuncSetAttribute(qkv_gemm, cudaFuncAttributeMaxDynamicSharedMemorySize, GEMM_SMEM);
    qkv_gemm<<<dim3(588, 6), 256, GEMM_SMEM>>>();

    int smem = (JT * KSH + DH * VTH) * (int)sizeof(__half);
    cudaFuncSetAttribute(attn_kernel, cudaFuncAttributeMaxDynamicSharedMemorySize, smem);
    attn_kernel<<<NWIN * NHEAD, 256, smem>>>();

    cudaFuncSetAttribute(out_gemm, cudaFuncAttributeMaxDynamicSharedMemorySize, GEMM_SMEM);
    out_gemm<<<dim3(588, 2), 256, GEMM_SMEM>>>(out);
}